// round 10
// baseline (speedup 1.0000x reference)
#include <cuda_runtime.h>
#include <cuda_bf16.h>
#include <cstdint>
#include <cstddef>

// Problem constants
#define BB 32
#define LL 512
#define HH 1024
#define HID 512
#define G4 2048   // 4*HID
#define TWOH 2048 // 2*H

// ---------------------------------------------------------------------------
// Scratch (static __device__ arrays)
// ---------------------------------------------------------------------------
__device__ __align__(16) float d_S[(size_t)BB * LL * LL];
__device__ __align__(16) float d_Gf[(size_t)LL * BB * G4];
__device__ __align__(16) float d_Gb[(size_t)LL * BB * G4];
__device__ __align__(16) float d_Qf[(size_t)LL * BB * G4];   // x@W2^T (time-major)
__device__ __align__(16) float d_Qb[(size_t)LL * BB * G4];
__device__ unsigned d_bar[2];
// h ping-pong in split bf16
__device__ __align__(16) __nv_bfloat16 d_hbf_hi[2][2][BB * HID];
__device__ __align__(16) __nv_bfloat16 d_hbf_lo[2][2][BB * HID];
// bf16 split operands
__device__ __align__(16) __nv_bfloat16 d_xhi[(size_t)BB * LL * HH];
__device__ __align__(16) __nv_bfloat16 d_xlo[(size_t)BB * LL * HH];
__device__ __align__(16) __nv_bfloat16 d_Shi[(size_t)BB * LL * LL];
__device__ __align__(16) __nv_bfloat16 d_Slo[(size_t)BB * LL * LL];
// Pt = W1 @ x^T per batch: [dir][b][n=2048][l=512], split bf16
__device__ __align__(16) __nv_bfloat16 d_Pthi[2][(size_t)BB * G4 * HID];
__device__ __align__(16) __nv_bfloat16 d_Ptlo[2][(size_t)BB * G4 * HID];
__device__ __align__(16) __nv_bfloat16 d_Whi[2][(size_t)G4 * TWOH];
__device__ __align__(16) __nv_bfloat16 d_Wlo[2][(size_t)G4 * TWOH];

// ---------------------------------------------------------------------------
// PTX helpers — base sm_100-safe (cp.async / ldmatrix / mma.sync)
// ---------------------------------------------------------------------------
__device__ __forceinline__ uint32_t smem_u32(const void* p) {
    uint32_t a;
    asm("{ .reg .u64 t; cvta.to.shared.u64 t, %1; cvt.u32.u64 %0, t; }" : "=r"(a) : "l"(p));
    return a;
}
__device__ __forceinline__ void cp_async16(uint32_t dst, const void* src) {
    asm volatile("cp.async.cg.shared.global [%0], [%1], 16;" :: "r"(dst), "l"(src));
}
#define CP_COMMIT() asm volatile("cp.async.commit_group;" ::: "memory")
#define CP_WAIT1()  asm volatile("cp.async.wait_group 1;" ::: "memory")
#define CP_WAIT0()  asm volatile("cp.async.wait_group 0;" ::: "memory")

__device__ __forceinline__ void ldm_x4(uint32_t* r, uint32_t a) {
    asm volatile("ldmatrix.sync.aligned.m8n8.x4.shared.b16 {%0,%1,%2,%3}, [%4];"
                 : "=r"(r[0]), "=r"(r[1]), "=r"(r[2]), "=r"(r[3]) : "r"(a));
}
__device__ __forceinline__ void mma_bf16(float* d, const uint32_t* a, const uint32_t* b) {
    asm volatile("mma.sync.aligned.m16n8k16.row.col.f32.bf16.bf16.f32 "
                 "{%0,%1,%2,%3}, {%4,%5,%6,%7}, {%8,%9}, {%0,%1,%2,%3};"
                 : "+f"(d[0]), "+f"(d[1]), "+f"(d[2]), "+f"(d[3])
                 : "r"(a[0]), "r"(a[1]), "r"(a[2]), "r"(a[3]), "r"(b[0]), "r"(b[1]));
}

#define SWZ128(off) ((off) ^ (((off) >> 3) & 0x70))

// ---------------------------------------------------------------------------
// init: zero split-h buffers + barrier counters
// ---------------------------------------------------------------------------
__global__ void init_state() {
    int i = blockIdx.x * blockDim.x + threadIdx.x;
    if (i < 2 * 2 * BB * HID) {
        ((__nv_bfloat16*)d_hbf_hi)[i] = __float2bfloat16(0.f);
        ((__nv_bfloat16*)d_hbf_lo)[i] = __float2bfloat16(0.f);
    }
    if (i < 2) d_bar[i] = 0u;
}

// ---------------------------------------------------------------------------
// Splits
// ---------------------------------------------------------------------------
__device__ __forceinline__ void split4(float4 v, __nv_bfloat162& H0, __nv_bfloat162& H1,
                                       __nv_bfloat162& L0, __nv_bfloat162& L1) {
    __nv_bfloat16 h0 = __float2bfloat16(v.x), h1 = __float2bfloat16(v.y);
    __nv_bfloat16 h2 = __float2bfloat16(v.z), h3 = __float2bfloat16(v.w);
    H0 = {h0, h1}; H1 = {h2, h3};
    L0 = {__float2bfloat16(v.x - __bfloat162float(h0)),
          __float2bfloat16(v.y - __bfloat162float(h1))};
    L1 = {__float2bfloat16(v.z - __bfloat162float(h2)),
          __float2bfloat16(v.w - __bfloat162float(h3))};
}

__global__ void __launch_bounds__(256) split_bf16(
    const float* __restrict__ src, __nv_bfloat16* __restrict__ hi,
    __nv_bfloat16* __restrict__ lo, size_t n4)
{
    size_t i = (size_t)blockIdx.x * 256 + threadIdx.x;
    if (i >= n4) return;
    __nv_bfloat162 H0, H1, L0, L1;
    split4(((const float4*)src)[i], H0, H1, L0, L1);
    ((__nv_bfloat162*)hi)[i * 2]     = H0;
    ((__nv_bfloat162*)hi)[i * 2 + 1] = H1;
    ((__nv_bfloat162*)lo)[i * 2]     = L0;
    ((__nv_bfloat162*)lo)[i * 2 + 1] = L1;
}

// ---------------------------------------------------------------------------
// Unified bf16-split tensor GEMM, 3-stage cp.async pipeline.
// C[m,n] = sum_k A[m,k]*B[n,k], 3 products (hi*hi + hi*lo + lo*hi).
// EPI=0: fp32 C batched (ldc/sC)
// EPI=1: split-bf16 out: Chi/Clo + z*sC + m*ldc + col
// EPI=2: time-major (m = b*512+t -> row t*32+b), + bias1+bias2
// EPI=3: batched time-major (row = m*32 + z), += Qadd
// ---------------------------------------------------------------------------
#define KC 64
#define TILEB 16384
#define STAGEB (4 * TILEB)
#define T3_DSMEM (1024 + 3 * STAGEB)

template <int EPI>
__global__ void __launch_bounds__(256) gemm_t3(
    const __nv_bfloat16* __restrict__ Ahi, const __nv_bfloat16* __restrict__ Alo,
    const __nv_bfloat16* __restrict__ Bhi, const __nv_bfloat16* __restrict__ Blo,
    int K, int lda, int ldb, size_t sA, size_t sB,
    float* __restrict__ Cf, int ldc, size_t sC,
    __nv_bfloat16* __restrict__ Chi, __nv_bfloat16* __restrict__ Clo,
    const float* __restrict__ bias1, const float* __restrict__ bias2,
    const float* __restrict__ Qadd)
{
    extern __shared__ char dsm[];
    char* basep = (char*)(((uintptr_t)dsm + 1023) & ~(uintptr_t)1023);
    const uint32_t sbase = smem_u32(basep);

    const int tid = threadIdx.x;
    const int wid = tid >> 5, lane = tid & 31;
    const int warp_m = wid >> 2, warp_n = wid & 3;
    const int m0 = blockIdx.y * 128, n0 = blockIdx.x * 128;
    const int z = blockIdx.z;
    Ahi += (size_t)z * sA; Alo += (size_t)z * sA;
    Bhi += (size_t)z * sB; Blo += (size_t)z * sB;

    float acc[4][4][4] = {};
    const int nchunk = K / KC;

    auto issue = [&](int chunk) {
        const uint32_t st = sbase + (chunk % 3) * STAGEB;
        const int kc = chunk * KC;
        #pragma unroll
        for (int i = 0; i < 4; i++) {
            int u = tid + i * 256;
            int r = u >> 3, cu = u & 7;
            uint32_t sw = SWZ128((uint32_t)(r * 128 + cu * 16));
            size_t ao = (size_t)(m0 + r) * lda + kc + cu * 8;
            size_t bo = (size_t)(n0 + r) * ldb + kc + cu * 8;
            cp_async16(st + sw,             Ahi + ao);
            cp_async16(st + TILEB + sw,     Alo + ao);
            cp_async16(st + 2 * TILEB + sw, Bhi + bo);
            cp_async16(st + 3 * TILEB + sw, Blo + bo);
        }
    };

    issue(0); CP_COMMIT();
    issue(1); CP_COMMIT();

    for (int c = 0; c < nchunk; c++) {
        CP_WAIT1();
        __syncthreads();
        if (c + 2 < nchunk) { issue(c + 2); CP_COMMIT(); }
        const uint32_t st = sbase + (c % 3) * STAGEB;

        #pragma unroll
        for (int ks = 0; ks < 4; ks++) {
            const int kb = ks * 32;
            uint32_t ah[4][4], al[4][4], bh[4][2], bl2[4][2];
            #pragma unroll
            for (int mt = 0; mt < 4; mt++) {
                int row = warp_m * 64 + mt * 16 + (lane & 15);
                uint32_t off = SWZ128((uint32_t)(row * 128 + kb + ((lane >> 4) * 16)));
                ldm_x4(ah[mt], st + off);
                ldm_x4(al[mt], st + TILEB + off);
            }
            #pragma unroll
            for (int ntp = 0; ntp < 2; ntp++) {
                int row = warp_n * 32 + ntp * 16 + ((lane >> 4) * 8) + (lane & 7);
                uint32_t off = SWZ128((uint32_t)(row * 128 + kb + (((lane >> 3) & 1) * 16)));
                uint32_t r4[4];
                ldm_x4(r4, st + 2 * TILEB + off);
                bh[2 * ntp][0] = r4[0]; bh[2 * ntp][1] = r4[1];
                bh[2 * ntp + 1][0] = r4[2]; bh[2 * ntp + 1][1] = r4[3];
                ldm_x4(r4, st + 3 * TILEB + off);
                bl2[2 * ntp][0] = r4[0]; bl2[2 * ntp][1] = r4[1];
                bl2[2 * ntp + 1][0] = r4[2]; bl2[2 * ntp + 1][1] = r4[3];
            }
            #pragma unroll
            for (int mt = 0; mt < 4; mt++)
                #pragma unroll
                for (int nt = 0; nt < 4; nt++) {
                    mma_bf16(acc[mt][nt], ah[mt], bh[nt]);
                    mma_bf16(acc[mt][nt], ah[mt], bl2[nt]);
                    mma_bf16(acc[mt][nt], al[mt], bh[nt]);
                }
        }
        __syncthreads();
    }

    // Epilogue
    const int g = lane >> 2, tc = lane & 3;
    #pragma unroll
    for (int nt = 0; nt < 4; nt++) {
        int col = n0 + warp_n * 32 + nt * 8 + tc * 2;
        float b0v = 0.f, b1v = 0.f;
        if (EPI == 2) {
            b0v = bias1[col] + bias2[col];
            b1v = bias1[col + 1] + bias2[col + 1];
        }
        #pragma unroll
        for (int mt = 0; mt < 4; mt++) {
            #pragma unroll
            for (int half = 0; half < 2; half++) {
                int ml = warp_m * 64 + mt * 16 + g + half * 8;
                float v0 = acc[mt][nt][half * 2] + b0v;
                float v1 = acc[mt][nt][half * 2 + 1] + b1v;
                if (EPI == 0) {
                    *(float2*)(Cf + (size_t)z * sC + (size_t)(m0 + ml) * ldc + col)
                        = make_float2(v0, v1);
                } else if (EPI == 1) {
                    size_t o = (size_t)z * sC + (size_t)(m0 + ml) * ldc + col;
                    __nv_bfloat16 h0 = __float2bfloat16(v0), h1 = __float2bfloat16(v1);
                    __nv_bfloat162 hv = {h0, h1};
                    __nv_bfloat162 lv = {__float2bfloat16(v0 - __bfloat162float(h0)),
                                         __float2bfloat16(v1 - __bfloat162float(h1))};
                    *(__nv_bfloat162*)(Chi + o) = hv;
                    *(__nv_bfloat162*)(Clo + o) = lv;
                } else if (EPI == 2) {
                    int m = m0 + ml;
                    int t = m & 511, b = m >> 9;
                    *(float2*)(Cf + ((size_t)t * 32 + b) * 2048 + col)
                        = make_float2(v0, v1);
                } else {
                    size_t idx = ((size_t)(m0 + ml) * 32 + z) * 2048 + col;
                    float2 q = *(const float2*)(Qadd + idx);
                    *(float2*)(Cf + idx) = make_float2(v0 + q.x, v1 + q.y);
                }
            }
        }
    }
}

// ---------------------------------------------------------------------------
// Masked softmax over last axis (512)
// ---------------------------------------------------------------------------
__global__ void __launch_bounds__(256) softmax512(float* __restrict__ S,
                                                  const float* __restrict__ mask)
{
    const int l = blockIdx.x, b = blockIdx.y;
    float* row = S + ((size_t)b * LL + l) * LL;
    const float* m = mask + (size_t)b * LL;
    const int tid = threadIdx.x;

    float m0 = m[tid], m1 = m[tid + 256];
    float v0 = (m0 > 0.5f) ? row[tid]       : -1e20f;
    float v1 = (m1 > 0.5f) ? row[tid + 256] : -1e20f;

    __shared__ float red[8];
    float mx = fmaxf(v0, v1);
    #pragma unroll
    for (int o = 16; o > 0; o >>= 1) mx = fmaxf(mx, __shfl_xor_sync(0xffffffffu, mx, o));
    if ((tid & 31) == 0) red[tid >> 5] = mx;
    __syncthreads();
    float bm = red[0];
    #pragma unroll
    for (int i = 1; i < 8; i++) bm = fmaxf(bm, red[i]);

    float e0 = expf(v0 - bm);
    float e1 = expf(v1 - bm);
    float sum = e0 + e1;
    #pragma unroll
    for (int o = 16; o > 0; o >>= 1) sum += __shfl_xor_sync(0xffffffffu, sum, o);
    __syncthreads();
    if ((tid & 31) == 0) red[tid >> 5] = sum;
    __syncthreads();
    float bs = 0.f;
    #pragma unroll
    for (int i = 0; i < 8; i++) bs += red[i];

    float inv = 1.0f / bs;
    row[tid]       = e0 * inv;
    row[tid + 256] = e1 * inv;
}

// ---------------------------------------------------------------------------
// Persistent bidirectional LSTM recurrence — TENSOR CORE (unchanged, passing)
// ---------------------------------------------------------------------------
__device__ __forceinline__ float sigm(float x) { return 1.0f / (1.0f + expf(-x)); }

#define LWH 0
#define LWL 32768
#define LHH 65536
#define LHL 98304
#define LSTM_DSMEM 132096

__global__ void __launch_bounds__(256, 1) lstm_rec(
    const float* __restrict__ Whf, const float* __restrict__ Whb,
    const int* __restrict__ x_len, float* __restrict__ out)
{
    extern __shared__ char lsm[];
    char* basep = (char*)(((uintptr_t)lsm + 1023) & ~(uintptr_t)1023);
    const uint32_t sbase = smem_u32(basep);

    __shared__ float gbuf[32][33];
    __shared__ float sG[32][36];
    __shared__ float cbuf[8][32];
    __shared__ float hown[8][32];
    __shared__ int s_len[32];

    const int tid = threadIdx.x;
    const int wid = tid >> 5, lane = tid & 31;
    const int warp_m = wid >> 2, warp_n = wid & 3;
    const int dir = blockIdx.x >> 6;
    const int u0 = (blockIdx.x & 63) * 8;
    const float* __restrict__ G = dir ? d_Gb : d_Gf;
    const float* __restrict__ W = dir ? Whb : Whf;

    if (tid < 32) s_len[tid] = x_len[tid];
    {
        int ul = tid & 7, b = tid >> 3;
        cbuf[ul][b] = 0.f; hown[ul][b] = 0.f;
    }

    {
        int lr = tid >> 3, kg = tid & 7;
        int r = (lr >> 3) * 512 + u0 + (lr & 7);
        const float4* wr = (const float4*)(W + (size_t)r * 512 + kg * 64);
        #pragma unroll
        for (int v = 0; v < 16; v++) {
            __nv_bfloat162 H0, H1, L0, L1;
            split4(wr[v], H0, H1, L0, L1);
            uint32_t off = kg * 4096 + SWZ128((uint32_t)(lr * 128 + v * 8));
            *(__nv_bfloat162*)(basep + LWH + off)     = H0;
            *(__nv_bfloat162*)(basep + LWH + off + 4) = H1;
            *(__nv_bfloat162*)(basep + LWL + off)     = L0;
            *(__nv_bfloat162*)(basep + LWL + off + 4) = L1;
        }
    }
    __syncthreads();

    const uint32_t aRowOff = (uint32_t)((warp_m * 16 + (lane & 15)) * 128 + (lane >> 4) * 16);
    const uint32_t bRowOff = (uint32_t)((warp_n * 8 + (lane & 7)) * 128 + ((lane >> 3) & 1) * 16);
    const uint32_t bTile = (lane < 16) ? (sbase + LWH) : (sbase + LWL);

    for (int s = 0; s < 512; s++) {
        const int t = dir ? (511 - s) : s;
        const int rb = s & 1, wb = rb ^ 1;
        const __nv_bfloat16* hgHi = &d_hbf_hi[dir][rb][0];
        const __nv_bfloat16* hgLo = &d_hbf_lo[dir][rb][0];

        #pragma unroll
        for (int i = 0; i < 8; i++) {
            int u = tid + i * 256;
            int b = u >> 6, ch = (u >> 3) & 7, cu = u & 7;
            uint32_t sw = ch * 4096 + SWZ128((uint32_t)(b * 128 + cu * 16));
            cp_async16(sbase + LHH + sw, hgHi + b * 512 + ch * 64 + cu * 8);
            cp_async16(sbase + LHL + sw, hgLo + b * 512 + ch * 64 + cu * 8);
        }
        CP_COMMIT();
        {
            int pair = tid >> 1, half = tid & 1;
            int b = pair >> 2, gate = pair & 3;
            const float* gsrc = G + ((size_t)t * 32 + b) * 2048 + gate * 512 + u0 + half * 4;
            cp_async16(smem_u32(&sG[b][gate * 8 + half * 4]), gsrc);
        }
        CP_COMMIT();
        CP_WAIT1();
        __syncthreads();

        float acc[4] = {0.f, 0.f, 0.f, 0.f};
        #pragma unroll 8
        for (int kst = 0; kst < 32; kst++) {
            uint32_t kc = (uint32_t)(kst >> 2) * 4096;
            uint32_t kb = (uint32_t)(kst & 3) * 32;
            uint32_t ao = kc + SWZ128(aRowOff + kb);
            uint32_t bo = kc + SWZ128(bRowOff + kb);
            uint32_t ah[4], al[4], bbx[4];
            ldm_x4(ah, sbase + LHH + ao);
            ldm_x4(al, sbase + LHL + ao);
            ldm_x4(bbx, bTile + bo);
            mma_bf16(acc, ah, bbx);
            mma_bf16(acc, ah, bbx + 2);
            mma_bf16(acc, al, bbx);
        }

        {
            int g = lane >> 2, tc = lane & 3;
            int n = warp_n * 8 + tc * 2, m = warp_m * 16 + g;
            gbuf[n][m]         = acc[0];
            gbuf[n + 1][m]     = acc[1];
            gbuf[n][m + 8]     = acc[2];
            gbuf[n + 1][m + 8] = acc[3];
        }
        CP_WAIT0();
        __syncthreads();

        {
            int b = tid >> 3, ul = tid & 7;
            float gi = gbuf[ul][b]      + sG[b][ul];
            float gf = gbuf[8 + ul][b]  + sG[b][8 + ul];
            float gg = gbuf[16 + ul][b] + sG[b][16 + ul];
            float go = gbuf[24 + ul][b] + sG[b][24 + ul];
            float c  = cbuf[ul][b];
            float nc = sigm(gf) * c + sigm(gi) * tanhf(gg);
            float nh = sigm(go) * tanhf(nc);
            bool valid = (t < s_len[b]);
            float hn = valid ? nh : hown[ul][b];
            float cn = valid ? nc : c;
            cbuf[ul][b] = cn;
            hown[ul][b] = hn;
            __nv_bfloat16 hhi = __float2bfloat16(hn);
            __nv_bfloat16 hlo = __float2bfloat16(hn - __bfloat162float(hhi));
            d_hbf_hi[dir][wb][b * 512 + u0 + ul] = hhi;
            d_hbf_lo[dir][wb][b * 512 + u0 + ul] = hlo;
            if (s == 511) out[(size_t)b * 1024 + dir * 512 + u0 + ul] = hn;
        }

        if (s == 511) break;

        __threadfence();
        __syncthreads();
        if (tid == 0) {
            atomicAdd(&d_bar[dir], 1u);
            const unsigned target = 64u * (unsigned)(s + 1);
            while (true) {
                unsigned v;
                asm volatile("ld.global.acquire.gpu.u32 %0, [%1];" : "=r"(v) : "l"(&d_bar[dir]));
                if (v >= target) break;
                __nanosleep(64);
            }
            __threadfence();
        }
        __syncthreads();
    }
}

// ---------------------------------------------------------------------------
// kernel_launch
// ---------------------------------------------------------------------------
extern "C" void kernel_launch(void* const* d_in, const int* in_sizes, int n_in,
                              void* d_out, int out_size)
{
    const float* x    = (const float*)d_in[0];
    const int*   xlen = (const int*)  d_in[1];
    const float* am   = (const float*)d_in[2];
    const float* Wif  = (const float*)d_in[3];
    const float* Whf  = (const float*)d_in[4];
    const float* bif  = (const float*)d_in[5];
    const float* bhf  = (const float*)d_in[6];
    const float* Wib  = (const float*)d_in[7];
    const float* Whb  = (const float*)d_in[8];
    const float* bib  = (const float*)d_in[9];
    const float* bhb  = (const float*)d_in[10];
    float* out = (float*)d_out;

    void *pS, *pGf, *pGb, *pQf, *pQb, *pxhi, *pxlo, *pShi, *pSlo,
         *pPthi, *pPtlo, *pWhi, *pWlo;
    cudaGetSymbolAddress(&pS,    d_S);
    cudaGetSymbolAddress(&pGf,   d_Gf);
    cudaGetSymbolAddress(&pGb,   d_Gb);
    cudaGetSymbolAddress(&pQf,   d_Qf);
    cudaGetSymbolAddress(&pQb,   d_Qb);
    cudaGetSymbolAddress(&pxhi,  d_xhi);
    cudaGetSymbolAddress(&pxlo,  d_xlo);
    cudaGetSymbolAddress(&pShi,  d_Shi);
    cudaGetSymbolAddress(&pSlo,  d_Slo);
    cudaGetSymbolAddress(&pPthi, d_Pthi);
    cudaGetSymbolAddress(&pPtlo, d_Ptlo);
    cudaGetSymbolAddress(&pWhi,  d_Whi);
    cudaGetSymbolAddress(&pWlo,  d_Wlo);
    float* S  = (float*)pS;
    float* Gf = (float*)pGf;
    float* Gb = (float*)pGb;
    float* Qf = (float*)pQf;
    float* Qb = (float*)pQb;
    __nv_bfloat16* xhi  = (__nv_bfloat16*)pxhi;
    __nv_bfloat16* xlo  = (__nv_bfloat16*)pxlo;
    __nv_bfloat16* Shi  = (__nv_bfloat16*)pShi;
    __nv_bfloat16* Slo  = (__nv_bfloat16*)pSlo;
    const size_t PT_STRIDE = (size_t)BB * G4 * HID;
    __nv_bfloat16* Pthi0 = (__nv_bfloat16*)pPthi;
    __nv_bfloat16* Pthi1 = Pthi0 + PT_STRIDE;
    __nv_bfloat16* Ptlo0 = (__nv_bfloat16*)pPtlo;
    __nv_bfloat16* Ptlo1 = Ptlo0 + PT_STRIDE;
    __nv_bfloat16* Whi0 = (__nv_bfloat16*)pWhi;
    __nv_bfloat16* Whi1 = Whi0 + (size_t)G4 * TWOH;
    __nv_bfloat16* Wlo0 = (__nv_bfloat16*)pWlo;
    __nv_bfloat16* Wlo1 = Wlo0 + (size_t)G4 * TWOH;

    cudaFuncSetAttribute(lstm_rec, cudaFuncAttributeMaxDynamicSharedMemorySize, LSTM_DSMEM);
    cudaFuncSetAttribute(gemm_t3<0>, cudaFuncAttributeMaxDynamicSharedMemorySize, T3_DSMEM);
    cudaFuncSetAttribute(gemm_t3<1>, cudaFuncAttributeMaxDynamicSharedMemorySize, T3_DSMEM);
    cudaFuncSetAttribute(gemm_t3<2>, cudaFuncAttributeMaxDynamicSharedMemorySize, T3_DSMEM);
    cudaFuncSetAttribute(gemm_t3<3>, cudaFuncAttributeMaxDynamicSharedMemorySize, T3_DSMEM);

    init_state<<<256, 256>>>();

    // split x -> xhi/xlo
    {
        size_t n4 = (size_t)BB * LL * HH / 4;
        split_bf16<<<(unsigned)((n4 + 255) / 256), 256>>>(x, xhi, xlo, n4);
    }
    // split weights (full W_ih; W1 = cols 0:1024, W2 = cols 1024:2048)
    {
        size_t w4 = (size_t)G4 * TWOH / 4;
        split_bf16<<<(unsigned)((w4 + 255) / 256), 256>>>(Wif, Whi0, Wlo0, w4);
        split_bf16<<<(unsigned)((w4 + 255) / 256), 256>>>(Wib, Whi1, Wlo1, w4);
    }

    // scores: S[b] = x_b * x_b^T  (K=1024)
    gemm_t3<0><<<dim3(LL / 128, LL / 128, BB), 256, T3_DSMEM>>>(
        xhi, xlo, xhi, xlo, HH, HH, HH,
        (size_t)LL * HH, (size_t)LL * HH,
        S, LL, (size_t)LL * LL, nullptr, nullptr, nullptr, nullptr, nullptr);

    softmax512<<<dim3(LL, BB), 256>>>(S, am);

    // split attention probs
    {
        size_t n4 = (size_t)BB * LL * LL / 4;
        split_bf16<<<(unsigned)((n4 + 255) / 256), 256>>>(S, Shi, Slo, n4);
    }

    // Pt_d[b][n][l] = sum_d W1_d[n][d] * x[b][l][d]   (M=2048, N=512, K=1024)
    // A = W1 (lda=2048, not batched), B = x_b (batched), split-bf16 out
    gemm_t3<1><<<dim3(HID / 128, G4 / 128, BB), 256, T3_DSMEM>>>(
        Whi0, Wlo0, xhi, xlo, HH, TWOH, HH,
        0, (size_t)LL * HH,
        nullptr, HID, (size_t)G4 * HID, Pthi0, Ptlo0, nullptr, nullptr, nullptr);
    gemm_t3<1><<<dim3(HID / 128, G4 / 128, BB), 256, T3_DSMEM>>>(
        Whi1, Wlo1, xhi, xlo, HH, TWOH, HH,
        0, (size_t)LL * HH,
        nullptr, HID, (size_t)G4 * HID, Pthi1, Ptlo1, nullptr, nullptr, nullptr);

    // Q_d = x @ W2_d^T + bias  (M=16384, N=2048, K=1024), time-major out
    gemm_t3<2><<<dim3(G4 / 128, (BB * LL) / 128, 1), 256, T3_DSMEM>>>(
        xhi, xlo, Whi0 + 1024, Wlo0 + 1024, HH, HH, TWOH, 0, 0,
        Qf, 0, 0, nullptr, nullptr, bif, bhf, nullptr);
    gemm_t3<2><<<dim3(G4 / 128, (BB * LL) / 128, 1), 256, T3_DSMEM>>>(
        xhi, xlo, Whi1 + 1024, Wlo1 + 1024, HH, HH, TWOH, 0, 0,
        Qb, 0, 0, nullptr, nullptr, bib, bhb, nullptr);

    // G_d = att @ Pt_d + Q_d  (batched: M=512 t, N=2048, K=512), time-major
    gemm_t3<3><<<dim3(G4 / 128, LL / 128, BB), 256, T3_DSMEM>>>(
        Shi, Slo, Pthi0, Ptlo0, LL, LL, HID,
        (size_t)LL * LL, (size_t)G4 * HID,
        Gf, 0, 0, nullptr, nullptr, nullptr, nullptr, Qf);
    gemm_t3<3><<<dim3(G4 / 128, LL / 128, BB), 256, T3_DSMEM>>>(
        Shi, Slo, Pthi1, Ptlo1, LL, LL, HID,
        (size_t)LL * LL, (size_t)G4 * HID,
        Gb, 0, 0, nullptr, nullptr, nullptr, nullptr, Qb);

    // Persistent bidirectional recurrence (tensor cores)
    lstm_rec<<<128, 256, LSTM_DSMEM>>>(Whf, Whb, xlen, out);
}

// round 11
// speedup vs baseline: 1.1652x; 1.1652x over previous
#include <cuda_runtime.h>
#include <cuda_bf16.h>
#include <cstdint>
#include <cstddef>

// Problem constants
#define BB 32
#define LL 512
#define HH 1024
#define HID 512
#define G4 2048   // 4*HID
#define TWOH 2048 // 2*H

// ---------------------------------------------------------------------------
// Scratch (static __device__ arrays)
// ---------------------------------------------------------------------------
__device__ __align__(16) float d_S[(size_t)BB * LL * LL];
__device__ __align__(16) float d_Gf[(size_t)LL * BB * G4];
__device__ __align__(16) float d_Gb[(size_t)LL * BB * G4];
__device__ unsigned d_bar[2];
// h ping-pong in split bf16
__device__ __align__(16) __nv_bfloat16 d_hbf_hi[2][2][BB * HID];
__device__ __align__(16) __nv_bfloat16 d_hbf_lo[2][2][BB * HID];
// bf16 split operands
__device__ __align__(16) __nv_bfloat16 d_xhi[(size_t)BB * LL * HH];
__device__ __align__(16) __nv_bfloat16 d_xlo[(size_t)BB * LL * HH];
__device__ __align__(16) __nv_bfloat16 d_xThi[(size_t)BB * HH * LL];
__device__ __align__(16) __nv_bfloat16 d_xTlo[(size_t)BB * HH * LL];
__device__ __align__(16) __nv_bfloat16 d_Shi[(size_t)BB * LL * LL];
__device__ __align__(16) __nv_bfloat16 d_Slo[(size_t)BB * LL * LL];
__device__ __align__(16) __nv_bfloat16 d_NXhi[(size_t)BB * LL * TWOH];
__device__ __align__(16) __nv_bfloat16 d_NXlo[(size_t)BB * LL * TWOH];
__device__ __align__(16) __nv_bfloat16 d_Whi[2][(size_t)G4 * TWOH];
__device__ __align__(16) __nv_bfloat16 d_Wlo[2][(size_t)G4 * TWOH];

// ---------------------------------------------------------------------------
// PTX helpers — base sm_100-safe (cp.async / ldmatrix / mma.sync)
// ---------------------------------------------------------------------------
__device__ __forceinline__ uint32_t smem_u32(const void* p) {
    uint32_t a;
    asm("{ .reg .u64 t; cvta.to.shared.u64 t, %1; cvt.u32.u64 %0, t; }" : "=r"(a) : "l"(p));
    return a;
}
__device__ __forceinline__ void cp_async16(uint32_t dst, const void* src) {
    asm volatile("cp.async.cg.shared.global [%0], [%1], 16;" :: "r"(dst), "l"(src));
}
#define CP_COMMIT() asm volatile("cp.async.commit_group;" ::: "memory")
#define CP_WAIT1()  asm volatile("cp.async.wait_group 1;" ::: "memory")
#define CP_WAIT0()  asm volatile("cp.async.wait_group 0;" ::: "memory")

__device__ __forceinline__ void ldm_x4(uint32_t* r, uint32_t a) {
    asm volatile("ldmatrix.sync.aligned.m8n8.x4.shared.b16 {%0,%1,%2,%3}, [%4];"
                 : "=r"(r[0]), "=r"(r[1]), "=r"(r[2]), "=r"(r[3]) : "r"(a));
}
__device__ __forceinline__ void mma_bf16(float* d, const uint32_t* a, const uint32_t* b) {
    asm volatile("mma.sync.aligned.m16n8k16.row.col.f32.bf16.bf16.f32 "
                 "{%0,%1,%2,%3}, {%4,%5,%6,%7}, {%8,%9}, {%0,%1,%2,%3};"
                 : "+f"(d[0]), "+f"(d[1]), "+f"(d[2]), "+f"(d[3])
                 : "r"(a[0]), "r"(a[1]), "r"(a[2]), "r"(a[3]), "r"(b[0]), "r"(b[1]));
}

#define SWZ128(off) ((off) ^ (((off) >> 3) & 0x70))

// ---------------------------------------------------------------------------
// init: zero split-h buffers + barrier counters
// ---------------------------------------------------------------------------
__global__ void init_state() {
    int i = blockIdx.x * blockDim.x + threadIdx.x;
    if (i < 2 * 2 * BB * HID) {
        ((__nv_bfloat16*)d_hbf_hi)[i] = __float2bfloat16(0.f);
        ((__nv_bfloat16*)d_hbf_lo)[i] = __float2bfloat16(0.f);
    }
    if (i < 2) d_bar[i] = 0u;
}

// ---------------------------------------------------------------------------
// Splits
// ---------------------------------------------------------------------------
__device__ __forceinline__ void split4(float4 v, __nv_bfloat162& H0, __nv_bfloat162& H1,
                                       __nv_bfloat162& L0, __nv_bfloat162& L1) {
    __nv_bfloat16 h0 = __float2bfloat16(v.x), h1 = __float2bfloat16(v.y);
    __nv_bfloat16 h2 = __float2bfloat16(v.z), h3 = __float2bfloat16(v.w);
    H0 = {h0, h1}; H1 = {h2, h3};
    L0 = {__float2bfloat16(v.x - __bfloat162float(h0)),
          __float2bfloat16(v.y - __bfloat162float(h1))};
    L1 = {__float2bfloat16(v.z - __bfloat162float(h2)),
          __float2bfloat16(v.w - __bfloat162float(h3))};
}

__global__ void __launch_bounds__(256) split_bf16(
    const float* __restrict__ src, __nv_bfloat16* __restrict__ hi,
    __nv_bfloat16* __restrict__ lo, size_t n4)
{
    size_t i = (size_t)blockIdx.x * 256 + threadIdx.x;
    if (i >= n4) return;
    __nv_bfloat162 H0, H1, L0, L1;
    split4(((const float4*)src)[i], H0, H1, L0, L1);
    ((__nv_bfloat162*)hi)[i * 2]     = H0;
    ((__nv_bfloat162*)hi)[i * 2 + 1] = H1;
    ((__nv_bfloat162*)lo)[i * 2]     = L0;
    ((__nv_bfloat162*)lo)[i * 2 + 1] = L1;
}

__global__ void __launch_bounds__(256) split_x(
    const float* __restrict__ x,
    __nv_bfloat16* __restrict__ xhi, __nv_bfloat16* __restrict__ xlo,
    __nv_bfloat16* __restrict__ NXhi, __nv_bfloat16* __restrict__ NXlo)
{
    size_t i = (size_t)blockIdx.x * 256 + threadIdx.x;
    if (i >= (size_t)BB * LL * HH / 4) return;
    __nv_bfloat162 H0, H1, L0, L1;
    split4(((const float4*)x)[i], H0, H1, L0, L1);
    ((__nv_bfloat162*)xhi)[i * 2]     = H0;
    ((__nv_bfloat162*)xhi)[i * 2 + 1] = H1;
    ((__nv_bfloat162*)xlo)[i * 2]     = L0;
    ((__nv_bfloat162*)xlo)[i * 2 + 1] = L1;
    size_t bl = i >> 8, d4 = i & 255;
    size_t o = bl * 1024 + 512 + d4 * 2;
    ((__nv_bfloat162*)NXhi)[o]     = H0;
    ((__nv_bfloat162*)NXhi)[o + 1] = H1;
    ((__nv_bfloat162*)NXlo)[o]     = L0;
    ((__nv_bfloat162*)NXlo)[o + 1] = L1;
}

__global__ void transpose_x(
    const __nv_bfloat16* __restrict__ hi, const __nv_bfloat16* __restrict__ lo,
    __nv_bfloat16* __restrict__ Thi, __nv_bfloat16* __restrict__ Tlo)
{
    __shared__ __nv_bfloat16 th[32][33], tl[32][33];
    const int b = blockIdx.z;
    const int d0 = blockIdx.x * 32, l0 = blockIdx.y * 32;
    const int tx = threadIdx.x, ty = threadIdx.y;
    const size_t si = (size_t)b * LL * HH;
    #pragma unroll
    for (int i = 0; i < 4; i++) {
        int l = ty + i * 8;
        th[l][tx] = hi[si + (size_t)(l0 + l) * HH + d0 + tx];
        tl[l][tx] = lo[si + (size_t)(l0 + l) * HH + d0 + tx];
    }
    __syncthreads();
    const size_t so = (size_t)b * HH * LL;
    #pragma unroll
    for (int i = 0; i < 4; i++) {
        int d = ty + i * 8;
        Thi[so + (size_t)(d0 + d) * LL + l0 + tx] = th[tx][d];
        Tlo[so + (size_t)(d0 + d) * LL + l0 + tx] = tl[tx][d];
    }
}

// ---------------------------------------------------------------------------
// Unified bf16-split tensor GEMM. Tile 128(M) x 64(N), 8 warps (2x4),
// warp tile 64x16, KC=64, 2-stage cp.async, 2 CTAs/SM.
// EPI=0: fp32 C batched; EPI=1: split-bf16 NX rows (ld TWOH);
// EPI=2: time-major gates + bias.
// ---------------------------------------------------------------------------
#define KC 64
#define TILEA 16384              // 128 rows x 128B
#define TILEBB 8192              // 64 rows x 128B
#define STAGEB (2 * TILEA + 2 * TILEBB)   // Ahi Alo Bhi Blo = 48KB
#define T3_DSMEM (1024 + 2 * STAGEB)      // ~97KB

template <int EPI>
__global__ void __launch_bounds__(256, 2) gemm_t3(
    const __nv_bfloat16* __restrict__ Ahi, const __nv_bfloat16* __restrict__ Alo,
    const __nv_bfloat16* __restrict__ Bhi, const __nv_bfloat16* __restrict__ Blo,
    int K, int lda, int ldb, size_t sA, size_t sB,
    float* __restrict__ Cf, int ldc, size_t sC,
    __nv_bfloat16* __restrict__ Chi, __nv_bfloat16* __restrict__ Clo,
    const float* __restrict__ bias1, const float* __restrict__ bias2)
{
    extern __shared__ char dsm[];
    char* basep = (char*)(((uintptr_t)dsm + 1023) & ~(uintptr_t)1023);
    const uint32_t sbase = smem_u32(basep);

    const int tid = threadIdx.x;
    const int wid = tid >> 5, lane = tid & 31;
    const int warp_m = wid >> 2, warp_n = wid & 3;
    const int m0 = blockIdx.y * 128, n0 = blockIdx.x * 64;
    const int z = blockIdx.z;
    Ahi += (size_t)z * sA; Alo += (size_t)z * sA;
    Bhi += (size_t)z * sB; Blo += (size_t)z * sB;

    float acc[4][2][4] = {};
    const int nchunk = K / KC;

    auto issue = [&](int chunk) {
        const uint32_t st = sbase + (chunk & 1) * STAGEB;
        const int kc = chunk * KC;
        #pragma unroll
        for (int i = 0; i < 4; i++) {
            int u = tid + i * 256;               // A: 1024 16B units
            int r = u >> 3, cu = u & 7;
            uint32_t sw = SWZ128((uint32_t)(r * 128 + cu * 16));
            size_t ao = (size_t)(m0 + r) * lda + kc + cu * 8;
            cp_async16(st + sw,         Ahi + ao);
            cp_async16(st + TILEA + sw, Alo + ao);
        }
        #pragma unroll
        for (int i = 0; i < 2; i++) {
            int u = tid + i * 256;               // B: 512 16B units
            int r = u >> 3, cu = u & 7;
            uint32_t sw = SWZ128((uint32_t)(r * 128 + cu * 16));
            size_t bo = (size_t)(n0 + r) * ldb + kc + cu * 8;
            cp_async16(st + 2 * TILEA + sw,          Bhi + bo);
            cp_async16(st + 2 * TILEA + TILEBB + sw, Blo + bo);
        }
    };

    issue(0); CP_COMMIT();

    for (int c = 0; c < nchunk; c++) {
        if (c + 1 < nchunk) issue(c + 1);
        CP_COMMIT();
        CP_WAIT1();
        __syncthreads();
        const uint32_t st = sbase + (c & 1) * STAGEB;

        #pragma unroll
        for (int ks = 0; ks < 4; ks++) {
            const int kb = ks * 32;
            uint32_t ah[4][4], al[4][4], bh[2][2], bl2[2][2];
            #pragma unroll
            for (int mt = 0; mt < 4; mt++) {
                int row = warp_m * 64 + mt * 16 + (lane & 15);
                uint32_t off = SWZ128((uint32_t)(row * 128 + kb + ((lane >> 4) * 16)));
                ldm_x4(ah[mt], st + off);
                ldm_x4(al[mt], st + TILEA + off);
            }
            {
                int row = warp_n * 16 + ((lane >> 4) * 8) + (lane & 7);
                uint32_t off = SWZ128((uint32_t)(row * 128 + kb + (((lane >> 3) & 1) * 16)));
                uint32_t r4[4];
                ldm_x4(r4, st + 2 * TILEA + off);
                bh[0][0] = r4[0]; bh[0][1] = r4[1];
                bh[1][0] = r4[2]; bh[1][1] = r4[3];
                ldm_x4(r4, st + 2 * TILEA + TILEBB + off);
                bl2[0][0] = r4[0]; bl2[0][1] = r4[1];
                bl2[1][0] = r4[2]; bl2[1][1] = r4[3];
            }
            #pragma unroll
            for (int mt = 0; mt < 4; mt++)
                #pragma unroll
                for (int nt = 0; nt < 2; nt++) {
                    mma_bf16(acc[mt][nt], ah[mt], bh[nt]);
                    mma_bf16(acc[mt][nt], ah[mt], bl2[nt]);
                    mma_bf16(acc[mt][nt], al[mt], bh[nt]);
                }
        }
        __syncthreads();
    }

    // Epilogue
    const int g = lane >> 2, tc = lane & 3;
    #pragma unroll
    for (int nt = 0; nt < 2; nt++) {
        int col = n0 + warp_n * 16 + nt * 8 + tc * 2;
        float b0v = 0.f, b1v = 0.f;
        if (EPI == 2) {
            b0v = bias1[col] + bias2[col];
            b1v = bias1[col + 1] + bias2[col + 1];
        }
        #pragma unroll
        for (int mt = 0; mt < 4; mt++) {
            #pragma unroll
            for (int half = 0; half < 2; half++) {
                int ml = warp_m * 64 + mt * 16 + g + half * 8;
                float v0 = acc[mt][nt][half * 2] + b0v;
                float v1 = acc[mt][nt][half * 2 + 1] + b1v;
                if (EPI == 0) {
                    *(float2*)(Cf + (size_t)z * sC + (size_t)(m0 + ml) * ldc + col)
                        = make_float2(v0, v1);
                } else if (EPI == 1) {
                    size_t row = (size_t)z * LL + m0 + ml;
                    __nv_bfloat16 h0 = __float2bfloat16(v0), h1 = __float2bfloat16(v1);
                    __nv_bfloat162 hv = {h0, h1};
                    __nv_bfloat162 lv = {__float2bfloat16(v0 - __bfloat162float(h0)),
                                         __float2bfloat16(v1 - __bfloat162float(h1))};
                    *(__nv_bfloat162*)(Chi + row * TWOH + col) = hv;
                    *(__nv_bfloat162*)(Clo + row * TWOH + col) = lv;
                } else {
                    int m = m0 + ml;
                    int t = m & 511, b = m >> 9;
                    *(float2*)(Cf + ((size_t)t * 32 + b) * 2048 + col)
                        = make_float2(v0, v1);
                }
            }
        }
    }
}

// ---------------------------------------------------------------------------
// Masked softmax over last axis (512)
// ---------------------------------------------------------------------------
__global__ void __launch_bounds__(256) softmax512(float* __restrict__ S,
                                                  const float* __restrict__ mask)
{
    const int l = blockIdx.x, b = blockIdx.y;
    float* row = S + ((size_t)b * LL + l) * LL;
    const float* m = mask + (size_t)b * LL;
    const int tid = threadIdx.x;

    float m0 = m[tid], m1 = m[tid + 256];
    float v0 = (m0 > 0.5f) ? row[tid]       : -1e20f;
    float v1 = (m1 > 0.5f) ? row[tid + 256] : -1e20f;

    __shared__ float red[8];
    float mx = fmaxf(v0, v1);
    #pragma unroll
    for (int o = 16; o > 0; o >>= 1) mx = fmaxf(mx, __shfl_xor_sync(0xffffffffu, mx, o));
    if ((tid & 31) == 0) red[tid >> 5] = mx;
    __syncthreads();
    float bm = red[0];
    #pragma unroll
    for (int i = 1; i < 8; i++) bm = fmaxf(bm, red[i]);

    float e0 = expf(v0 - bm);
    float e1 = expf(v1 - bm);
    float sum = e0 + e1;
    #pragma unroll
    for (int o = 16; o > 0; o >>= 1) sum += __shfl_xor_sync(0xffffffffu, sum, o);
    __syncthreads();
    if ((tid & 31) == 0) red[tid >> 5] = sum;
    __syncthreads();
    float bs = 0.f;
    #pragma unroll
    for (int i = 0; i < 8; i++) bs += red[i];

    float inv = 1.0f / bs;
    row[tid]       = e0 * inv;
    row[tid + 256] = e1 * inv;
}

// ---------------------------------------------------------------------------
// Persistent bidirectional LSTM recurrence — TENSOR CORE (unchanged, passing)
// ---------------------------------------------------------------------------
__device__ __forceinline__ float sigm(float x) { return 1.0f / (1.0f + expf(-x)); }

#define LWH 0
#define LWL 32768
#define LHH 65536
#define LHL 98304
#define LSTM_DSMEM 132096

__global__ void __launch_bounds__(256, 1) lstm_rec(
    const float* __restrict__ Whf, const float* __restrict__ Whb,
    const int* __restrict__ x_len, float* __restrict__ out)
{
    extern __shared__ char lsm[];
    char* basep = (char*)(((uintptr_t)lsm + 1023) & ~(uintptr_t)1023);
    const uint32_t sbase = smem_u32(basep);

    __shared__ float gbuf[32][33];
    __shared__ float sG[32][36];
    __shared__ float cbuf[8][32];
    __shared__ float hown[8][32];
    __shared__ int s_len[32];

    const int tid = threadIdx.x;
    const int wid = tid >> 5, lane = tid & 31;
    const int warp_m = wid >> 2, warp_n = wid & 3;
    const int dir = blockIdx.x >> 6;
    const int u0 = (blockIdx.x & 63) * 8;
    const float* __restrict__ G = dir ? d_Gb : d_Gf;
    const float* __restrict__ W = dir ? Whb : Whf;

    if (tid < 32) s_len[tid] = x_len[tid];
    {
        int ul = tid & 7, b = tid >> 3;
        cbuf[ul][b] = 0.f; hown[ul][b] = 0.f;
    }

    {
        int lr = tid >> 3, kg = tid & 7;
        int r = (lr >> 3) * 512 + u0 + (lr & 7);
        const float4* wr = (const float4*)(W + (size_t)r * 512 + kg * 64);
        #pragma unroll
        for (int v = 0; v < 16; v++) {
            __nv_bfloat162 H0, H1, L0, L1;
            split4(wr[v], H0, H1, L0, L1);
            uint32_t off = kg * 4096 + SWZ128((uint32_t)(lr * 128 + v * 8));
            *(__nv_bfloat162*)(basep + LWH + off)     = H0;
            *(__nv_bfloat162*)(basep + LWH + off + 4) = H1;
            *(__nv_bfloat162*)(basep + LWL + off)     = L0;
            *(__nv_bfloat162*)(basep + LWL + off + 4) = L1;
        }
    }
    __syncthreads();

    const uint32_t aRowOff = (uint32_t)((warp_m * 16 + (lane & 15)) * 128 + (lane >> 4) * 16);
    const uint32_t bRowOff = (uint32_t)((warp_n * 8 + (lane & 7)) * 128 + ((lane >> 3) & 1) * 16);
    const uint32_t bTile = (lane < 16) ? (sbase + LWH) : (sbase + LWL);

    for (int s = 0; s < 512; s++) {
        const int t = dir ? (511 - s) : s;
        const int rb = s & 1, wb = rb ^ 1;
        const __nv_bfloat16* hgHi = &d_hbf_hi[dir][rb][0];
        const __nv_bfloat16* hgLo = &d_hbf_lo[dir][rb][0];

        #pragma unroll
        for (int i = 0; i < 8; i++) {
            int u = tid + i * 256;
            int b = u >> 6, ch = (u >> 3) & 7, cu = u & 7;
            uint32_t sw = ch * 4096 + SWZ128((uint32_t)(b * 128 + cu * 16));
            cp_async16(sbase + LHH + sw, hgHi + b * 512 + ch * 64 + cu * 8);
            cp_async16(sbase + LHL + sw, hgLo + b * 512 + ch * 64 + cu * 8);
        }
        CP_COMMIT();
        {
            int pair = tid >> 1, half = tid & 1;
            int b = pair >> 2, gate = pair & 3;
            const float* gsrc = G + ((size_t)t * 32 + b) * 2048 + gate * 512 + u0 + half * 4;
            cp_async16(smem_u32(&sG[b][gate * 8 + half * 4]), gsrc);
        }
        CP_COMMIT();
        CP_WAIT1();
        __syncthreads();

        float acc[4] = {0.f, 0.f, 0.f, 0.f};
        #pragma unroll 8
        for (int kst = 0; kst < 32; kst++) {
            uint32_t kc = (uint32_t)(kst >> 2) * 4096;
            uint32_t kb = (uint32_t)(kst & 3) * 32;
            uint32_t ao = kc + SWZ128(aRowOff + kb);
            uint32_t bo = kc + SWZ128(bRowOff + kb);
            uint32_t ah[4], al[4], bbx[4];
            ldm_x4(ah, sbase + LHH + ao);
            ldm_x4(al, sbase + LHL + ao);
            ldm_x4(bbx, bTile + bo);
            mma_bf16(acc, ah, bbx);
            mma_bf16(acc, ah, bbx + 2);
            mma_bf16(acc, al, bbx);
        }

        {
            int g = lane >> 2, tc = lane & 3;
            int n = warp_n * 8 + tc * 2, m = warp_m * 16 + g;
            gbuf[n][m]         = acc[0];
            gbuf[n + 1][m]     = acc[1];
            gbuf[n][m + 8]     = acc[2];
            gbuf[n + 1][m + 8] = acc[3];
        }
        CP_WAIT0();
        __syncthreads();

        {
            int b = tid >> 3, ul = tid & 7;
            float gi = gbuf[ul][b]      + sG[b][ul];
            float gf = gbuf[8 + ul][b]  + sG[b][8 + ul];
            float gg = gbuf[16 + ul][b] + sG[b][16 + ul];
            float go = gbuf[24 + ul][b] + sG[b][24 + ul];
            float c  = cbuf[ul][b];
            float nc = sigm(gf) * c + sigm(gi) * tanhf(gg);
            float nh = sigm(go) * tanhf(nc);
            bool valid = (t < s_len[b]);
            float hn = valid ? nh : hown[ul][b];
            float cn = valid ? nc : c;
            cbuf[ul][b] = cn;
            hown[ul][b] = hn;
            __nv_bfloat16 hhi = __float2bfloat16(hn);
            __nv_bfloat16 hlo = __float2bfloat16(hn - __bfloat162float(hhi));
            d_hbf_hi[dir][wb][b * 512 + u0 + ul] = hhi;
            d_hbf_lo[dir][wb][b * 512 + u0 + ul] = hlo;
            if (s == 511) out[(size_t)b * 1024 + dir * 512 + u0 + ul] = hn;
        }

        if (s == 511) break;

        __threadfence();
        __syncthreads();
        if (tid == 0) {
            atomicAdd(&d_bar[dir], 1u);
            const unsigned target = 64u * (unsigned)(s + 1);
            while (true) {
                unsigned v;
                asm volatile("ld.global.acquire.gpu.u32 %0, [%1];" : "=r"(v) : "l"(&d_bar[dir]));
                if (v >= target) break;
                __nanosleep(64);
            }
            __threadfence();
        }
        __syncthreads();
    }
}

// ---------------------------------------------------------------------------
// kernel_launch
// ---------------------------------------------------------------------------
extern "C" void kernel_launch(void* const* d_in, const int* in_sizes, int n_in,
                              void* d_out, int out_size)
{
    const float* x    = (const float*)d_in[0];
    const int*   xlen = (const int*)  d_in[1];
    const float* am   = (const float*)d_in[2];
    const float* Wif  = (const float*)d_in[3];
    const float* Whf  = (const float*)d_in[4];
    const float* bif  = (const float*)d_in[5];
    const float* bhf  = (const float*)d_in[6];
    const float* Wib  = (const float*)d_in[7];
    const float* Whb  = (const float*)d_in[8];
    const float* bib  = (const float*)d_in[9];
    const float* bhb  = (const float*)d_in[10];
    float* out = (float*)d_out;

    void *pS, *pGf, *pGb, *pxhi, *pxlo, *pxThi, *pxTlo, *pShi, *pSlo,
         *pNXhi, *pNXlo, *pWhi, *pWlo;
    cudaGetSymbolAddress(&pS,    d_S);
    cudaGetSymbolAddress(&pGf,   d_Gf);
    cudaGetSymbolAddress(&pGb,   d_Gb);
    cudaGetSymbolAddress(&pxhi,  d_xhi);
    cudaGetSymbolAddress(&pxlo,  d_xlo);
    cudaGetSymbolAddress(&pxThi, d_xThi);
    cudaGetSymbolAddress(&pxTlo, d_xTlo);
    cudaGetSymbolAddress(&pShi,  d_Shi);
    cudaGetSymbolAddress(&pSlo,  d_Slo);
    cudaGetSymbolAddress(&pNXhi, d_NXhi);
    cudaGetSymbolAddress(&pNXlo, d_NXlo);
    cudaGetSymbolAddress(&pWhi,  d_Whi);
    cudaGetSymbolAddress(&pWlo,  d_Wlo);
    float* S = (float*)pS;
    float* Gf = (float*)pGf;
    float* Gb = (float*)pGb;
    __nv_bfloat16* xhi  = (__nv_bfloat16*)pxhi;
    __nv_bfloat16* xlo  = (__nv_bfloat16*)pxlo;
    __nv_bfloat16* xThi = (__nv_bfloat16*)pxThi;
    __nv_bfloat16* xTlo = (__nv_bfloat16*)pxTlo;
    __nv_bfloat16* Shi  = (__nv_bfloat16*)pShi;
    __nv_bfloat16* Slo  = (__nv_bfloat16*)pSlo;
    __nv_bfloat16* NXhi = (__nv_bfloat16*)pNXhi;
    __nv_bfloat16* NXlo = (__nv_bfloat16*)pNXlo;
    __nv_bfloat16* Whi0 = (__nv_bfloat16*)pWhi;
    __nv_bfloat16* Whi1 = Whi0 + (size_t)G4 * TWOH;
    __nv_bfloat16* Wlo0 = (__nv_bfloat16*)pWlo;
    __nv_bfloat16* Wlo1 = Wlo0 + (size_t)G4 * TWOH;

    cudaFuncSetAttribute(lstm_rec, cudaFuncAttributeMaxDynamicSharedMemorySize, LSTM_DSMEM);
    cudaFuncSetAttribute(gemm_t3<0>, cudaFuncAttributeMaxDynamicSharedMemorySize, T3_DSMEM);
    cudaFuncSetAttribute(gemm_t3<1>, cudaFuncAttributeMaxDynamicSharedMemorySize, T3_DSMEM);
    cudaFuncSetAttribute(gemm_t3<2>, cudaFuncAttributeMaxDynamicSharedMemorySize, T3_DSMEM);

    init_state<<<256, 256>>>();

    {
        size_t n4 = (size_t)BB * LL * HH / 4;
        split_x<<<(unsigned)((n4 + 255) / 256), 256>>>(x, xhi, xlo, NXhi, NXlo);
    }

    transpose_x<<<dim3(HH / 32, LL / 32, BB), dim3(32, 8)>>>(xhi, xlo, xThi, xTlo);

    // scores: S[b] = x_b * x_b^T  (K=1024)
    gemm_t3<0><<<dim3(LL / 64, LL / 128, BB), 256, T3_DSMEM>>>(
        xhi, xlo, xhi, xlo, HH, HH, HH,
        (size_t)LL * HH, (size_t)LL * HH,
        S, LL, (size_t)LL * LL, nullptr, nullptr, nullptr, nullptr);

    softmax512<<<dim3(LL, BB), 256>>>(S, am);

    {
        size_t n4 = (size_t)BB * LL * LL / 4;
        split_bf16<<<(unsigned)((n4 + 255) / 256), 256>>>(S, Shi, Slo, n4);
    }

    // att @ x -> NX[:, :, 0:1024] split-bf16 (K=512, B = x^T)
    gemm_t3<1><<<dim3(HH / 64, LL / 128, BB), 256, T3_DSMEM>>>(
        Shi, Slo, xThi, xTlo, LL, LL, LL,
        (size_t)LL * LL, (size_t)HH * LL,
        nullptr, 0, 0, NXhi, NXlo, nullptr, nullptr);

    {
        size_t w4 = (size_t)G4 * TWOH / 4;
        split_bf16<<<(unsigned)((w4 + 255) / 256), 256>>>(Wif, Whi0, Wlo0, w4);
        split_bf16<<<(unsigned)((w4 + 255) / 256), 256>>>(Wib, Whi1, Wlo1, w4);
    }

    // gate precompute (K=2048), time-major out with bias
    gemm_t3<2><<<dim3(G4 / 64, (BB * LL) / 128, 1), 256, T3_DSMEM>>>(
        NXhi, NXlo, Whi0, Wlo0, TWOH, TWOH, TWOH, 0, 0,
        Gf, 0, 0, nullptr, nullptr, bif, bhf);
    gemm_t3<2><<<dim3(G4 / 64, (BB * LL) / 128, 1), 256, T3_DSMEM>>>(
        NXhi, NXlo, Whi1, Wlo1, TWOH, TWOH, TWOH, 0, 0,
        Gb, 0, 0, nullptr, nullptr, bib, bhb);

    // Persistent bidirectional recurrence (tensor cores)
    lstm_rec<<<128, 256, LSTM_DSMEM>>>(Whf, Whb, xlen, out);
}